// round 1
// baseline (speedup 1.0000x reference)
#include <cuda_runtime.h>
#include <math.h>
#include <stdint.h>

// GraphRNN: 2-layer LayerNorm-GRU scan.
// B=16, T=24, N=207, D=512, L=2, G=3*D=1536.
namespace {
constexpr int B_ = 16, T_ = 24, N_ = 207, D_ = 512, G_ = 1536;
constexpr int MR  = B_ * N_;        // 3312 rows per timestep
constexpr int MB_ = B_ * T_ * N_;   // 79488 rows (all timesteps)
constexpr int BM = 128, BNt = 128, BK = 16, TM = 8, TN = 8; // 256 thr
}

// Scratch (static device globals; no allocation in kernel_launch)
__device__ float g_gi0[(size_t)MB_ * G_];   // precomputed x@Wi0+bi0 for all T (488 MB)
__device__ float g_gh0[(size_t)MR * G_];
__device__ float g_gi1[(size_t)MR * G_];
__device__ float g_gh1[(size_t)MR * G_];
__device__ float g_h0s[(size_t)MR * D_];
__device__ float g_h1s[(size_t)MR * D_];

// ---------------------------------------------------------------------------
// SGEMM core: C[M,1536] = A[M,512] @ W[512,1536] + bias
// ---------------------------------------------------------------------------
__device__ __forceinline__ void gemm_core(const float* __restrict__ A,
                                          const float* __restrict__ W,
                                          const float* __restrict__ bias,
                                          float* __restrict__ C, int M)
{
    __shared__ float As[BK * BM];   // transposed: As[k][m]
    __shared__ float Ws[BK * BNt];  // Ws[k][n]
    const int tid  = threadIdx.x;
    const int brow = blockIdx.y * BM;
    const int bcol = blockIdx.x * BNt;
    const int ty = tid >> 4, tx = tid & 15;

    float acc[TM][TN];
#pragma unroll
    for (int i = 0; i < TM; i++)
#pragma unroll
        for (int j = 0; j < TN; j++) acc[i][j] = 0.f;

    for (int k0 = 0; k0 < D_; k0 += BK) {
#pragma unroll
        for (int l = 0; l < 2; l++) {
            int f = tid + l * 256;                 // 0..511 float4 slots
            // A tile: 128 rows x 16 k
            int r = f >> 2, kk4 = f & 3;
            float4 v = make_float4(0.f, 0.f, 0.f, 0.f);
            int grow = brow + r;
            if (grow < M)
                v = *reinterpret_cast<const float4*>(A + (size_t)grow * D_ + k0 + kk4 * 4);
            As[(kk4 * 4 + 0) * BM + r] = v.x;
            As[(kk4 * 4 + 1) * BM + r] = v.y;
            As[(kk4 * 4 + 2) * BM + r] = v.z;
            As[(kk4 * 4 + 3) * BM + r] = v.w;
            // W tile: 16 k x 128 cols
            int kr = f >> 5, c4 = f & 31;
            float4 w = *reinterpret_cast<const float4*>(W + (size_t)(k0 + kr) * G_ + bcol + c4 * 4);
            *reinterpret_cast<float4*>(&Ws[kr * BNt + c4 * 4]) = w;
        }
        __syncthreads();
#pragma unroll
        for (int kk = 0; kk < BK; kk++) {
            float a[TM], bb[TN];
            float4 a0 = *reinterpret_cast<const float4*>(&As[kk * BM + ty * TM]);
            float4 a1 = *reinterpret_cast<const float4*>(&As[kk * BM + ty * TM + 4]);
            float4 b0 = *reinterpret_cast<const float4*>(&Ws[kk * BNt + tx * TN]);
            float4 b1 = *reinterpret_cast<const float4*>(&Ws[kk * BNt + tx * TN + 4]);
            a[0]=a0.x; a[1]=a0.y; a[2]=a0.z; a[3]=a0.w;
            a[4]=a1.x; a[5]=a1.y; a[6]=a1.z; a[7]=a1.w;
            bb[0]=b0.x; bb[1]=b0.y; bb[2]=b0.z; bb[3]=b0.w;
            bb[4]=b1.x; bb[5]=b1.y; bb[6]=b1.z; bb[7]=b1.w;
#pragma unroll
            for (int i = 0; i < TM; i++)
#pragma unroll
                for (int j = 0; j < TN; j++)
                    acc[i][j] = fmaf(a[i], bb[j], acc[i][j]);
        }
        __syncthreads();
    }

#pragma unroll
    for (int i = 0; i < TM; i++) {
        int grow = brow + ty * TM + i;
        if (grow >= M) continue;
#pragma unroll
        for (int j = 0; j < TN; j += 4) {
            int gcol = bcol + tx * TN + j;
            float4 o;
            o.x = acc[i][j]     + bias[gcol];
            o.y = acc[i][j + 1] + bias[gcol + 1];
            o.z = acc[i][j + 2] + bias[gcol + 2];
            o.w = acc[i][j + 3] + bias[gcol + 3];
            *reinterpret_cast<float4*>(C + (size_t)grow * G_ + gcol) = o;
        }
    }
}

__global__ void __launch_bounds__(256, 2)
sgemm_kernel(const float* __restrict__ A, const float* __restrict__ W,
             const float* __restrict__ bias, float* __restrict__ C, int M)
{
    gemm_core(A, W, bias, C, M);
}

// Three GEMMs in one launch via blockIdx.z (M = MR for all).
__global__ void __launch_bounds__(256, 2)
gemm3_kernel(const float* A0, const float* W0, const float* b0, float* C0,
             const float* A1, const float* W1, const float* b1, float* C1,
             const float* A2, const float* W2, const float* b2, float* C2)
{
    const float* A; const float* W; const float* bias; float* C;
    if (blockIdx.z == 0)      { A = A0; W = W0; bias = b0; C = C0; }
    else if (blockIdx.z == 1) { A = A1; W = W1; bias = b1; C = C1; }
    else                      { A = A2; W = W2; bias = b2; C = C2; }
    gemm_core(A, W, bias, C, MR);
}

// ---------------------------------------------------------------------------
// Fused GRU cell + LayerNorm. One block per (b,n) row, 128 threads x 4 elems.
// ---------------------------------------------------------------------------
__global__ void __launch_bounds__(128)
gru_cell(const float* __restrict__ gi_base, int t, int time_layout,
         const float* __restrict__ gh, float* __restrict__ h,
         const float* __restrict__ gamma, const float* __restrict__ beta,
         float* __restrict__ out2, int t_out)
{
    int m = blockIdx.x;
    int b = m / N_, n = m % N_;
    const float* gi = gi_base +
        (time_layout ? ((size_t)(b * T_ + t) * N_ + n) : (size_t)m) * G_;
    const float* ghr = gh + (size_t)m * G_;
    float* hr = h + (size_t)m * D_;
    int tid = threadIdx.x;

    float o[4];
    float s = 0.f, s2 = 0.f;
#pragma unroll
    for (int i = 0; i < 4; i++) {
        int d = tid + i * 128;
        float ir  = gi[d], iz  = gi[d + D_],  inn = gi[d + 2 * D_];
        float hrv = ghr[d], hzv = ghr[d + D_], hnv = ghr[d + 2 * D_];
        float r = 1.f / (1.f + expf(-(ir + hrv)));
        float z = 1.f / (1.f + expf(-(iz + hzv)));
        float nv = tanhf(inn + r * hnv);
        float hv = hr[d];
        float ov = nv + z * (hv - nv);
        o[i] = ov;
        s += ov; s2 += ov * ov;
    }
#pragma unroll
    for (int off = 16; off > 0; off >>= 1) {
        s  += __shfl_xor_sync(0xffffffffu, s,  off);
        s2 += __shfl_xor_sync(0xffffffffu, s2, off);
    }
    __shared__ float sh[4], sh2[4];
    int w = tid >> 5;
    if ((tid & 31) == 0) { sh[w] = s; sh2[w] = s2; }
    __syncthreads();
    s  = sh[0]  + sh[1]  + sh[2]  + sh[3];
    s2 = sh2[0] + sh2[1] + sh2[2] + sh2[3];
    float mu  = s * (1.f / D_);
    float var = s2 * (1.f / D_) - mu * mu;
    float inv = rsqrtf(var + 1e-5f);

    float* o2 = out2 ? out2 + ((size_t)(b * T_ + t_out) * N_ + n) * D_ : nullptr;
#pragma unroll
    for (int i = 0; i < 4; i++) {
        int d = tid + i * 128;
        float y = (o[i] - mu) * inv * gamma[d] + beta[d];
        hr[d] = y;
        if (o2) o2[d] = y;
    }
}

// h0 [B, L, N, D] -> per-layer state buffers [B*N, D]
__global__ void init_h_kernel(const float* __restrict__ h0,
                              float* __restrict__ h0s, float* __restrict__ h1s)
{
    int i = blockIdx.x * blockDim.x + threadIdx.x;
    if (i >= 2 * MR * D_) return;
    int d = i % D_;
    int r = i / D_;
    int n = r % N_; r /= N_;
    int l = r % 2;
    int b = r / 2;
    float v = h0[i];
    float* dst = (l == 0) ? h0s : h1s;
    dst[((size_t)b * N_ + n) * D_ + d] = v;
}

// state buffers -> hidden output [B, L, N, D]
__global__ void write_hidden_kernel(const float* __restrict__ h0s,
                                    const float* __restrict__ h1s,
                                    float* __restrict__ dst)
{
    int i = blockIdx.x * blockDim.x + threadIdx.x;
    if (i >= 2 * MR * D_) return;
    int d = i % D_;
    int r = i / D_;
    int n = r % N_; r /= N_;
    int l = r % 2;
    int b = r / 2;
    const float* src = (l == 0) ? h0s : h1s;
    dst[i] = src[((size_t)b * N_ + n) * D_ + d];
}

// ---------------------------------------------------------------------------
extern "C" void kernel_launch(void* const* d_in, const int* in_sizes, int n_in,
                              void* d_out, int out_size)
{
    (void)in_sizes; (void)n_in;
    const float* x     = (const float*)d_in[0];
    const float* h0    = (const float*)d_in[1];
    const float* Wi    = (const float*)d_in[2];
    const float* bi    = (const float*)d_in[3];
    const float* Wh    = (const float*)d_in[4];
    const float* bh    = (const float*)d_in[5];
    const float* gamma = (const float*)d_in[6];
    const float* beta  = (const float*)d_in[7];
    float* out = (float*)d_out;

    float *gi0, *gh0, *gi1, *gh1, *h0s, *h1s;
    cudaGetSymbolAddress((void**)&gi0, g_gi0);
    cudaGetSymbolAddress((void**)&gh0, g_gh0);
    cudaGetSymbolAddress((void**)&gi1, g_gi1);
    cudaGetSymbolAddress((void**)&gh1, g_gh1);
    cudaGetSymbolAddress((void**)&h0s, g_h0s);
    cudaGetSymbolAddress((void**)&h1s, g_h1s);

    const float* Wi1 = Wi + (size_t)D_ * G_;
    const float* Wh1 = Wh + (size_t)D_ * G_;

    // init hidden state buffers
    {
        int tot = 2 * MR * D_;
        init_h_kernel<<<(tot + 255) / 256, 256>>>(h0, h0s, h1s);
    }

    // Hoisted layer-0 input GEMM over all timesteps: gi0 = x @ Wi0 + bi0
    sgemm_kernel<<<dim3(G_ / BNt, (MB_ + BM - 1) / BM), 256>>>(x, Wi, bi, gi0, MB_);

    // GH0(0) = h0_state @ Wh0 + bh0, then cell0(0)
    sgemm_kernel<<<dim3(G_ / BNt, (MR + BM - 1) / BM), 256>>>(h0s, Wh, bh, gh0, MR);
    gru_cell<<<MR, 128>>>(gi0, 0, 1, gh0, h0s, gamma, beta, (float*)nullptr, 0);

    for (int t = 0; t < T_; t++) {
        int nz = (t == T_ - 1) ? 2 : 3;
        // z=0: GI1(t) = out0(t) @ Wi1 ; z=1: GH1(t) = h1 @ Wh1 ;
        // z=2: GH0(t+1) = out0(t) @ Wh0
        gemm3_kernel<<<dim3(G_ / BNt, (MR + BM - 1) / BM, nz), 256>>>(
            h0s, Wi1, bi + G_, gi1,
            h1s, Wh1, bh + G_, gh1,
            h0s, Wh,  bh,      gh0);
        // cell1(t): updates h1 state and writes output[:, t]
        gru_cell<<<MR, 128>>>(gi1, 0, 0, gh1, h1s, gamma + D_, beta + D_, out, t);
        // cell0(t+1): updates h0 state
        if (t + 1 < T_)
            gru_cell<<<MR, 128>>>(gi0, t + 1, 1, gh0, h0s, gamma, beta,
                                  (float*)nullptr, 0);
    }

    long long need = (long long)MB_ * D_ + (long long)2 * MR * D_;
    if ((long long)out_size >= need) {
        int tot = 2 * MR * D_;
        write_hidden_kernel<<<(tot + 255) / 256, 256>>>(h0s, h1s,
                                                        out + (size_t)MB_ * D_);
    }
}

// round 3
// speedup vs baseline: 1.4838x; 1.4838x over previous
#include <cuda_runtime.h>
#include <math.h>
#include <stdint.h>

// GraphRNN: 2-layer LayerNorm-GRU scan. B=16, T=24, N=207, D=512, G=1536.
// R3: GEMMs via mma.sync m16n8k8 tf32 with 3xTF32 split (fp32-accurate).
namespace {
constexpr int B_ = 16, T_ = 24, N_ = 207, D_ = 512, G_ = 1536;
constexpr int MR  = B_ * N_;        // 3312 rows per timestep
constexpr int MRP = 3328;           // padded: 26*128
constexpr int MB_ = B_ * T_ * N_;   // 79488 = 621*128

constexpr int BK = 32;              // k-chunk
constexpr int NCHUNK = D_ / BK;     // 16
constexpr int LDP = 36;             // padded row stride (floats): bank map 4m+k
constexpr int STAGE_F = 128 * LDP;  // 4608 floats per tile stage
constexpr int SMEM_BYTES = 4 * STAGE_F * 4;  // As0,As1,Bs0,Bs1 = 73728 B

constexpr size_t GD = (size_t)G_ * D_;
}

// ---------------- scratch (device globals) ----------------
__device__ float g_gi0[(size_t)MB_ * G_];
__device__ float g_gh0[(size_t)MRP * G_];
__device__ float g_gi1[(size_t)MRP * G_];
__device__ float g_gh1[(size_t)MRP * G_];
__device__ float g_h0s[(size_t)MRP * D_];   // pad rows stay 0
__device__ float g_h1s[(size_t)MRP * D_];
__device__ float g_Wt[4 * GD];              // Wi0^T, Wi1^T, Wh0^T, Wh1^T [1536,512]

// ---------------- helpers ----------------
__device__ __forceinline__ uint32_t smem_u32(const void* p) {
    uint32_t a;
    asm("{ .reg .u64 t; cvta.to.shared.u64 t, %1; cvt.u32.u64 %0, t; }"
        : "=r"(a) : "l"(p));
    return a;
}
#define CP_ASYNC16(dst, src) \
    asm volatile("cp.async.cg.shared.global [%0], [%1], 16;" :: "r"(dst), "l"(src))
#define CP_COMMIT() asm volatile("cp.async.commit_group;" ::: "memory")
template <int N>
__device__ __forceinline__ void cp_wait() {
    asm volatile("cp.async.wait_group %0;" :: "n"(N) : "memory");
}

__device__ __forceinline__ uint32_t cvt_tf32(float x) {
    uint32_t r;
    asm("cvt.rna.tf32.f32 %0, %1;" : "=r"(r) : "f"(x));
    return r;
}
__device__ __forceinline__ void split_tf32(float x, uint32_t& hi, uint32_t& lo) {
    hi = cvt_tf32(x);
    lo = cvt_tf32(x - __uint_as_float(hi));
}

#define MMA_TF32(d, a, b0, b1)                                              \
    asm volatile("mma.sync.aligned.m16n8k8.row.col.f32.tf32.tf32.f32 "      \
        "{%0,%1,%2,%3}, {%4,%5,%6,%7}, {%8,%9}, {%0,%1,%2,%3};"             \
        : "+f"((d)[0]), "+f"((d)[1]), "+f"((d)[2]), "+f"((d)[3])            \
        : "r"((a)[0]), "r"((a)[1]), "r"((a)[2]), "r"((a)[3]),               \
          "r"(b0), "r"(b1))

// ---------------------------------------------------------------------------
// tf32 GEMM core: C tile (128x128) = A[brow..,512] @ Wt[bcol..,512]^T + bias
// Both A and Wt are K-major with stride 512. 256 threads, 8 warps 4(m)x2(n).
// ---------------------------------------------------------------------------
__device__ __forceinline__ void load_stage(uint32_t sA, uint32_t sB,
                                           const float* __restrict__ Ag,
                                           const float* __restrict__ Bg,
                                           int k0, int tid) {
#pragma unroll
    for (int i = 0; i < 4; i++) {
        int s = tid + i * 256;          // 0..1023 float4 slots per tile
        int row = s >> 3, c4 = s & 7;
        uint32_t doff = (uint32_t)(row * LDP + c4 * 4) * 4u;
        CP_ASYNC16(sA + doff, Ag + (size_t)row * D_ + k0 + c4 * 4);
        CP_ASYNC16(sB + doff, Bg + (size_t)row * D_ + k0 + c4 * 4);
    }
}

__device__ __forceinline__ void tf32_gemm_core(const float* __restrict__ A,
                                               const float* __restrict__ Wt,
                                               const float* __restrict__ bias,
                                               float* __restrict__ C) {
    extern __shared__ float sm[];
    float* AsT[2] = { sm, sm + STAGE_F };
    float* BsT[2] = { sm + 2 * STAGE_F, sm + 3 * STAGE_F };
    const uint32_t sA0 = smem_u32(AsT[0]), sA1 = smem_u32(AsT[1]);
    const uint32_t sB0 = smem_u32(BsT[0]), sB1 = smem_u32(BsT[1]);

    const int tid  = threadIdx.x;
    const int lane = tid & 31, warp = tid >> 5;
    const int warpM = warp & 3, warpN = warp >> 2;
    const int r  = lane >> 2;       // 0..7
    const int qk = lane & 3;        // 0..3
    const int brow = blockIdx.y * 128;
    const int bcol = blockIdx.x * 128;

    const float* Ag = A  + (size_t)brow * D_;
    const float* Bg = Wt + (size_t)bcol * D_;

    float acc[2][8][4];
#pragma unroll
    for (int mt = 0; mt < 2; mt++)
#pragma unroll
        for (int nt = 0; nt < 8; nt++)
#pragma unroll
            for (int i = 0; i < 4; i++) acc[mt][nt][i] = 0.f;

    load_stage(sA0, sB0, Ag, Bg, 0, tid);
    CP_COMMIT();
    load_stage(sA1, sB1, Ag, Bg, BK, tid);
    CP_COMMIT();

    for (int ch = 0; ch < NCHUNK; ch++) {
        if (ch < NCHUNK - 1) cp_wait<1>(); else cp_wait<0>();
        __syncthreads();
        const int cur = ch & 1;
        const float* as  = AsT[cur] + (size_t)(warpM * 32 + r) * LDP;
        const float* bsb = BsT[cur] + (size_t)(warpN * 64 + r) * LDP;

#pragma unroll
        for (int k8 = 0; k8 < 4; k8++) {
            const int kk = k8 * 8 + qk;
            uint32_t ah[2][4], al[2][4];
#pragma unroll
            for (int mt = 0; mt < 2; mt++) {
                const float* p = as + mt * 16 * LDP;
                split_tf32(p[kk],                ah[mt][0], al[mt][0]);
                split_tf32(p[8 * LDP + kk],      ah[mt][1], al[mt][1]);
                split_tf32(p[kk + 4],            ah[mt][2], al[mt][2]);
                split_tf32(p[8 * LDP + kk + 4],  ah[mt][3], al[mt][3]);
            }
#pragma unroll
            for (int nt = 0; nt < 8; nt++) {
                const float* q = bsb + nt * 8 * LDP;
                uint32_t bh0, bl0, bh1, bl1;
                split_tf32(q[kk],     bh0, bl0);
                split_tf32(q[kk + 4], bh1, bl1);
#pragma unroll
                for (int mt = 0; mt < 2; mt++) {
                    MMA_TF32(acc[mt][nt], al[mt], bh0, bh1);
                    MMA_TF32(acc[mt][nt], ah[mt], bl0, bl1);
                    MMA_TF32(acc[mt][nt], ah[mt], bh0, bh1);
                }
            }
        }
        __syncthreads();
        if (ch + 2 < NCHUNK) {
            load_stage(cur ? sA1 : sA0, cur ? sB1 : sB0, Ag, Bg, (ch + 2) * BK, tid);
            CP_COMMIT();
        }
    }

    // epilogue: acc + bias -> C (float2 stores; quads cover 32B)
    const int q2 = qk * 2;
#pragma unroll
    for (int mt = 0; mt < 2; mt++) {
        const int row0 = brow + warpM * 32 + mt * 16 + r;
#pragma unroll
        for (int nt = 0; nt < 8; nt++) {
            const int col = bcol + warpN * 64 + nt * 8 + q2;
            const float2 bv = *reinterpret_cast<const float2*>(bias + col);
            float2 v0 = make_float2(acc[mt][nt][0] + bv.x, acc[mt][nt][1] + bv.y);
            float2 v1 = make_float2(acc[mt][nt][2] + bv.x, acc[mt][nt][3] + bv.y);
            *reinterpret_cast<float2*>(C + (size_t)row0 * G_ + col) = v0;
            *reinterpret_cast<float2*>(C + (size_t)(row0 + 8) * G_ + col) = v1;
        }
    }
}

__global__ void __launch_bounds__(256, 2)
tf32_gemm1_kernel(const float* __restrict__ A, const float* __restrict__ Wt,
                  const float* __restrict__ bias, float* __restrict__ C) {
    tf32_gemm_core(A, Wt, bias, C);
}

__global__ void __launch_bounds__(256, 2)
tf32_gemm3_kernel(const float* A0, const float* W0, const float* b0, float* C0,
                  const float* A1, const float* W1, const float* b1, float* C1,
                  const float* A2, const float* W2, const float* b2, float* C2) {
    const float* A; const float* W; const float* bias; float* C;
    if (blockIdx.z == 0)      { A = A0; W = W0; bias = b0; C = C0; }
    else if (blockIdx.z == 1) { A = A1; W = W1; bias = b1; C = C1; }
    else                      { A = A2; W = W2; bias = b2; C = C2; }
    tf32_gemm_core(A, W, bias, C);
}

// ---------------------------------------------------------------------------
// Weight transpose: Wt[z][n][k] = W[z][k][n], z: Wi0,Wi1,Wh0,Wh1
// ---------------------------------------------------------------------------
__global__ void transpose_kernel(const float* __restrict__ Wi,
                                 const float* __restrict__ Wh,
                                 float* __restrict__ Wt) {
    __shared__ float tile[32][33];
    int z = blockIdx.z;
    const float* src = (z < 2 ? Wi : Wh) + (size_t)(z & 1) * D_ * G_;
    float* dst = Wt + (size_t)z * GD;
    int n0 = blockIdx.x * 32, k0 = blockIdx.y * 32;
#pragma unroll
    for (int i = 0; i < 4; i++) {
        int k = k0 + threadIdx.y * 4 + i;
        tile[threadIdx.y * 4 + i][threadIdx.x] = src[(size_t)k * G_ + n0 + threadIdx.x];
    }
    __syncthreads();
#pragma unroll
    for (int i = 0; i < 4; i++) {
        int n = n0 + threadIdx.y * 4 + i;
        dst[(size_t)n * D_ + k0 + threadIdx.x] = tile[threadIdx.x][threadIdx.y * 4 + i];
    }
}

// ---------------------------------------------------------------------------
// Fused GRU cell + LayerNorm (128 thr x float4 = 512 = D)
// ---------------------------------------------------------------------------
__device__ __forceinline__ float sigf(float v) { return 1.f / (1.f + expf(-v)); }

__global__ void __launch_bounds__(128)
gru_cell(const float* __restrict__ gi_base, int t, int time_layout,
         const float* __restrict__ gh, float* __restrict__ h,
         const float* __restrict__ gamma, const float* __restrict__ beta,
         float* __restrict__ out2, int t_out) {
    int m = blockIdx.x;
    int b = m / N_, n = m % N_;
    const float* gi = gi_base +
        (time_layout ? ((size_t)(b * T_ + t) * N_ + n) : (size_t)m) * G_;
    const float4* gi4 = reinterpret_cast<const float4*>(gi);
    const float4* gh4 = reinterpret_cast<const float4*>(gh + (size_t)m * G_);
    float4* h4 = reinterpret_cast<float4*>(h + (size_t)m * D_);
    int tid = threadIdx.x;

    float4 ir = gi4[tid], iz = gi4[128 + tid], inn = gi4[256 + tid];
    float4 hr = gh4[tid], hz = gh4[128 + tid], hn = gh4[256 + tid];
    float4 hv = h4[tid];

    float o[4];
    {
        float rr, z, nv;
        rr = sigf(ir.x + hr.x); z = sigf(iz.x + hz.x); nv = tanhf(inn.x + rr * hn.x);
        o[0] = nv + z * (hv.x - nv);
        rr = sigf(ir.y + hr.y); z = sigf(iz.y + hz.y); nv = tanhf(inn.y + rr * hn.y);
        o[1] = nv + z * (hv.y - nv);
        rr = sigf(ir.z + hr.z); z = sigf(iz.z + hz.z); nv = tanhf(inn.z + rr * hn.z);
        o[2] = nv + z * (hv.z - nv);
        rr = sigf(ir.w + hr.w); z = sigf(iz.w + hz.w); nv = tanhf(inn.w + rr * hn.w);
        o[3] = nv + z * (hv.w - nv);
    }
    float s = o[0] + o[1] + o[2] + o[3];
    float s2 = o[0]*o[0] + o[1]*o[1] + o[2]*o[2] + o[3]*o[3];
#pragma unroll
    for (int off = 16; off > 0; off >>= 1) {
        s  += __shfl_xor_sync(0xffffffffu, s,  off);
        s2 += __shfl_xor_sync(0xffffffffu, s2, off);
    }
    __shared__ float sh[4], sh2[4];
    int w = tid >> 5;
    if ((tid & 31) == 0) { sh[w] = s; sh2[w] = s2; }
    __syncthreads();
    s  = sh[0]  + sh[1]  + sh[2]  + sh[3];
    s2 = sh2[0] + sh2[1] + sh2[2] + sh2[3];
    float mu  = s * (1.f / D_);
    float var = s2 * (1.f / D_) - mu * mu;
    float inv = rsqrtf(var + 1e-5f);

    const float4 g4 = reinterpret_cast<const float4*>(gamma)[tid];
    const float4 b4 = reinterpret_cast<const float4*>(beta)[tid];
    float4 y;
    y.x = (o[0] - mu) * inv * g4.x + b4.x;
    y.y = (o[1] - mu) * inv * g4.y + b4.y;
    y.z = (o[2] - mu) * inv * g4.z + b4.z;
    y.w = (o[3] - mu) * inv * g4.w + b4.w;
    h4[tid] = y;
    if (out2)
        reinterpret_cast<float4*>(out2 + ((size_t)(b * T_ + t_out) * N_ + n) * D_)[tid] = y;
}

// ---------------------------------------------------------------------------
__global__ void init_h_kernel(const float* __restrict__ h0,
                              float* __restrict__ h0s, float* __restrict__ h1s) {
    int i = blockIdx.x * blockDim.x + threadIdx.x;
    if (i >= 2 * MR * D_) return;
    int d = i % D_;
    int r = i / D_;
    int n = r % N_; r /= N_;
    int l = r % 2;
    int b = r / 2;
    float v = h0[i];
    float* dst = (l == 0) ? h0s : h1s;
    dst[((size_t)b * N_ + n) * D_ + d] = v;
}

__global__ void write_hidden_kernel(const float* __restrict__ h0s,
                                    const float* __restrict__ h1s,
                                    float* __restrict__ dst) {
    int i = blockIdx.x * blockDim.x + threadIdx.x;
    if (i >= 2 * MR * D_) return;
    int d = i % D_;
    int r = i / D_;
    int n = r % N_; r /= N_;
    int l = r % 2;
    int b = r / 2;
    const float* src = (l == 0) ? h0s : h1s;
    dst[i] = src[((size_t)b * N_ + n) * D_ + d];
}

// ---------------------------------------------------------------------------
extern "C" void kernel_launch(void* const* d_in, const int* in_sizes, int n_in,
                              void* d_out, int out_size) {
    (void)in_sizes; (void)n_in;
    const float* x     = (const float*)d_in[0];
    const float* h0    = (const float*)d_in[1];
    const float* Wi    = (const float*)d_in[2];
    const float* bi    = (const float*)d_in[3];
    const float* Wh    = (const float*)d_in[4];
    const float* bh    = (const float*)d_in[5];
    const float* gamma = (const float*)d_in[6];
    const float* beta  = (const float*)d_in[7];
    float* out = (float*)d_out;

    float *gi0, *gh0, *gi1, *gh1, *h0s, *h1s, *Wt;
    cudaGetSymbolAddress((void**)&gi0, g_gi0);
    cudaGetSymbolAddress((void**)&gh0, g_gh0);
    cudaGetSymbolAddress((void**)&gi1, g_gi1);
    cudaGetSymbolAddress((void**)&gh1, g_gh1);
    cudaGetSymbolAddress((void**)&h0s, g_h0s);
    cudaGetSymbolAddress((void**)&h1s, g_h1s);
    cudaGetSymbolAddress((void**)&Wt,  g_Wt);

    cudaFuncSetAttribute(tf32_gemm1_kernel,
                         cudaFuncAttributeMaxDynamicSharedMemorySize, SMEM_BYTES);
    cudaFuncSetAttribute(tf32_gemm3_kernel,
                         cudaFuncAttributeMaxDynamicSharedMemorySize, SMEM_BYTES);

    const float* Wi0t = Wt;
    const float* Wi1t = Wt + GD;
    const float* Wh0t = Wt + 2 * GD;
    const float* Wh1t = Wt + 3 * GD;

    transpose_kernel<<<dim3(G_ / 32, D_ / 32, 4), dim3(32, 8)>>>(Wi, Wh, Wt);
    {
        int tot = 2 * MR * D_;
        init_h_kernel<<<(tot + 255) / 256, 256>>>(h0, h0s, h1s);
    }

    // Hoisted layer-0 input GEMM (all timesteps): gi0 = x @ Wi0 + bi0
    tf32_gemm1_kernel<<<dim3(G_ / 128, MB_ / 128), 256, SMEM_BYTES>>>(x, Wi0t, bi, gi0);

    // GH0(0) = h0 @ Wh0 + bh0, then cell0(0)
    tf32_gemm1_kernel<<<dim3(G_ / 128, MRP / 128), 256, SMEM_BYTES>>>(h0s, Wh0t, bh, gh0);
    gru_cell<<<MR, 128>>>(gi0, 0, 1, gh0, h0s, gamma, beta, (float*)nullptr, 0);

    for (int t = 0; t < T_; t++) {
        int nz = (t == T_ - 1) ? 2 : 3;
        // z=0: GI1(t)=out0(t)@Wi1 ; z=1: GH1(t)=h1@Wh1 ; z=2: GH0(t+1)=out0(t)@Wh0
        tf32_gemm3_kernel<<<dim3(G_ / 128, MRP / 128, nz), 256, SMEM_BYTES>>>(
            h0s, Wi1t, bi + G_, gi1,
            h1s, Wh1t, bh + G_, gh1,
            h0s, Wh0t, bh,      gh0);
        gru_cell<<<MR, 128>>>(gi1, 0, 0, gh1, h1s, gamma + D_, beta + D_, out, t);
        if (t + 1 < T_)
            gru_cell<<<MR, 128>>>(gi0, t + 1, 1, gh0, h0s, gamma, beta,
                                  (float*)nullptr, 0);
    }

    long long need = (long long)MB_ * D_ + (long long)2 * MR * D_;
    if ((long long)out_size >= need) {
        int tot = 2 * MR * D_;
        write_hidden_kernel<<<(tot + 255) / 256, 256>>>(h0s, h1s,
                                                        out + (size_t)MB_ * D_);
    }
}

// round 4
// speedup vs baseline: 1.4902x; 1.0043x over previous
#include <cuda_runtime.h>
#include <math.h>
#include <stdint.h>

// GraphRNN: 2-layer LayerNorm-GRU scan. B=16, T=24, N=207, D=512, G=1536.
// R4: mma.sync m16n8k8 tf32, 3xTF32 split; weight hi/lo pre-split in global.
namespace {
constexpr int B_ = 16, T_ = 24, N_ = 207, D_ = 512, G_ = 1536;
constexpr int MR  = B_ * N_;        // 3312 rows per timestep
constexpr int MRP = 3328;           // padded: 26*128
constexpr int MB_ = B_ * T_ * N_;   // 79488 = 621*128

constexpr int BK = 32;              // k-chunk
constexpr int NCHUNK = D_ / BK;     // 16
constexpr int LDP = 36;             // padded row stride: bank=(4r+qk)%32 bijective
constexpr int STAGE_F = 128 * LDP;  // 4608 words per tile
constexpr int SMEM_BYTES = 6 * STAGE_F * 4;  // A0,A1,Bh0,Bh1,Bl0,Bl1 = 110592 B

constexpr size_t GD = (size_t)G_ * D_;
}

// ---------------- scratch (device globals) ----------------
__device__ float    g_gi0[(size_t)MB_ * G_];
__device__ float    g_gh0[(size_t)MRP * G_];
__device__ float    g_gi1[(size_t)MRP * G_];
__device__ float    g_gh1[(size_t)MRP * G_];
__device__ float    g_h0s[(size_t)MRP * D_];   // pad rows stay 0
__device__ float    g_h1s[(size_t)MRP * D_];
__device__ uint32_t g_Wth[4 * GD];             // tf32-hi of Wi0^T,Wi1^T,Wh0^T,Wh1^T
__device__ uint32_t g_Wtl[4 * GD];             // tf32-lo

// ---------------- helpers ----------------
__device__ __forceinline__ uint32_t smem_u32(const void* p) {
    uint32_t a;
    asm("{ .reg .u64 t; cvta.to.shared.u64 t, %1; cvt.u32.u64 %0, t; }"
        : "=r"(a) : "l"(p));
    return a;
}
#define CP_ASYNC16(dst, src) \
    asm volatile("cp.async.cg.shared.global [%0], [%1], 16;" :: "r"(dst), "l"(src))
#define CP_COMMIT() asm volatile("cp.async.commit_group;" ::: "memory")
template <int N>
__device__ __forceinline__ void cp_wait() {
    asm volatile("cp.async.wait_group %0;" :: "n"(N) : "memory");
}

__device__ __forceinline__ uint32_t cvt_tf32(float x) {
    uint32_t r;
    asm("cvt.rna.tf32.f32 %0, %1;" : "=r"(r) : "f"(x));
    return r;
}
__device__ __forceinline__ void split_tf32(float x, uint32_t& hi, uint32_t& lo) {
    hi = cvt_tf32(x);
    lo = cvt_tf32(x - __uint_as_float(hi));
}

#define MMA_TF32(d, a, b0, b1)                                              \
    asm volatile("mma.sync.aligned.m16n8k8.row.col.f32.tf32.tf32.f32 "      \
        "{%0,%1,%2,%3}, {%4,%5,%6,%7}, {%8,%9}, {%0,%1,%2,%3};"             \
        : "+f"((d)[0]), "+f"((d)[1]), "+f"((d)[2]), "+f"((d)[3])            \
        : "r"((a)[0]), "r"((a)[1]), "r"((a)[2]), "r"((a)[3]),               \
          "r"(b0), "r"(b1))

// ---------------------------------------------------------------------------
// GEMM core: C tile (128x128) = A[brow..,512] @ Wt[bcol..,512]^T + bias
// A fp32 K-major; weights pre-split (hi/lo tf32). 256 thr, 8 warps 4(m)x2(n).
// ---------------------------------------------------------------------------
__device__ __forceinline__ void load_stage(uint32_t sA, uint32_t sBh, uint32_t sBl,
                                           const float* __restrict__ Ag,
                                           const uint32_t* __restrict__ Bhg,
                                           const uint32_t* __restrict__ Blg,
                                           int k0, int tid) {
#pragma unroll
    for (int i = 0; i < 4; i++) {
        int s = tid + i * 256;          // 0..1023 16B slots per tile
        int row = s >> 3, c4 = s & 7;
        uint32_t doff = (uint32_t)(row * LDP + c4 * 4) * 4u;
        size_t goff = (size_t)row * D_ + k0 + c4 * 4;
        CP_ASYNC16(sA  + doff, Ag  + goff);
        CP_ASYNC16(sBh + doff, Bhg + goff);
        CP_ASYNC16(sBl + doff, Blg + goff);
    }
}

__device__ __forceinline__ void tf32_gemm_core(const float* __restrict__ A,
                                               const uint32_t* __restrict__ Bh,
                                               const uint32_t* __restrict__ Bl,
                                               const float* __restrict__ bias,
                                               float* __restrict__ C) {
    extern __shared__ float sm[];
    float*    AsT[2] = { sm, sm + STAGE_F };
    uint32_t* BhT[2] = { (uint32_t*)sm + 2 * STAGE_F, (uint32_t*)sm + 3 * STAGE_F };
    uint32_t* BlT[2] = { (uint32_t*)sm + 4 * STAGE_F, (uint32_t*)sm + 5 * STAGE_F };

    const int tid  = threadIdx.x;
    const int lane = tid & 31, warp = tid >> 5;
    const int warpM = warp & 3, warpN = warp >> 2;
    const int r  = lane >> 2;       // 0..7
    const int qk = lane & 3;        // 0..3
    const int brow = blockIdx.y * 128;
    const int bcol = blockIdx.x * 128;

    const float*    Ag  = A  + (size_t)brow * D_;
    const uint32_t* Bhg = Bh + (size_t)bcol * D_;
    const uint32_t* Blg = Bl + (size_t)bcol * D_;

    float acc[2][8][4];
#pragma unroll
    for (int mt = 0; mt < 2; mt++)
#pragma unroll
        for (int nt = 0; nt < 8; nt++)
#pragma unroll
            for (int i = 0; i < 4; i++) acc[mt][nt][i] = 0.f;

    load_stage(smem_u32(AsT[0]), smem_u32(BhT[0]), smem_u32(BlT[0]), Ag, Bhg, Blg, 0, tid);
    CP_COMMIT();
    load_stage(smem_u32(AsT[1]), smem_u32(BhT[1]), smem_u32(BlT[1]), Ag, Bhg, Blg, BK, tid);
    CP_COMMIT();

    for (int ch = 0; ch < NCHUNK; ch++) {
        if (ch < NCHUNK - 1) cp_wait<1>(); else cp_wait<0>();
        __syncthreads();
        const int cur = ch & 1;
        const float*    as  = AsT[cur] + (size_t)(warpM * 32 + r) * LDP;
        const uint32_t* bhb = BhT[cur] + (size_t)(warpN * 64 + r) * LDP;
        const uint32_t* blb = BlT[cur] + (size_t)(warpN * 64 + r) * LDP;

#pragma unroll
        for (int k8 = 0; k8 < 4; k8++) {
            const int kk = k8 * 8 + qk;
            uint32_t ah[2][4], al[2][4];
#pragma unroll
            for (int mt = 0; mt < 2; mt++) {
                const float* p = as + mt * 16 * LDP;
                split_tf32(p[kk],                ah[mt][0], al[mt][0]);
                split_tf32(p[8 * LDP + kk],      ah[mt][1], al[mt][1]);
                split_tf32(p[kk + 4],            ah[mt][2], al[mt][2]);
                split_tf32(p[8 * LDP + kk + 4],  ah[mt][3], al[mt][3]);
            }
#pragma unroll
            for (int nt = 0; nt < 8; nt++) {
                const uint32_t* qh = bhb + nt * 8 * LDP;
                const uint32_t* ql = blb + nt * 8 * LDP;
                uint32_t bh0 = qh[kk], bh1 = qh[kk + 4];
                uint32_t bl0 = ql[kk], bl1 = ql[kk + 4];
#pragma unroll
                for (int mt = 0; mt < 2; mt++) {
                    MMA_TF32(acc[mt][nt], al[mt], bh0, bh1);
                    MMA_TF32(acc[mt][nt], ah[mt], bl0, bl1);
                    MMA_TF32(acc[mt][nt], ah[mt], bh0, bh1);
                }
            }
        }
        __syncthreads();
        if (ch + 2 < NCHUNK) {
            load_stage(smem_u32(AsT[cur]), smem_u32(BhT[cur]), smem_u32(BlT[cur]),
                       Ag, Bhg, Blg, (ch + 2) * BK, tid);
            CP_COMMIT();
        }
    }

    // epilogue: acc + bias -> C (float2 stores)
    const int q2 = qk * 2;
#pragma unroll
    for (int mt = 0; mt < 2; mt++) {
        const int row0 = brow + warpM * 32 + mt * 16 + r;
#pragma unroll
        for (int nt = 0; nt < 8; nt++) {
            const int col = bcol + warpN * 64 + nt * 8 + q2;
            const float2 bv = *reinterpret_cast<const float2*>(bias + col);
            float2 v0 = make_float2(acc[mt][nt][0] + bv.x, acc[mt][nt][1] + bv.y);
            float2 v1 = make_float2(acc[mt][nt][2] + bv.x, acc[mt][nt][3] + bv.y);
            *reinterpret_cast<float2*>(C + (size_t)row0 * G_ + col) = v0;
            *reinterpret_cast<float2*>(C + (size_t)(row0 + 8) * G_ + col) = v1;
        }
    }
}

__global__ void __launch_bounds__(256, 2)
tf32_gemm1_kernel(const float* __restrict__ A, const uint32_t* __restrict__ Bh,
                  const uint32_t* __restrict__ Bl, const float* __restrict__ bias,
                  float* __restrict__ C) {
    tf32_gemm_core(A, Bh, Bl, bias, C);
}

__global__ void __launch_bounds__(256, 2)
tf32_gemm3_kernel(const float* A0, const uint32_t* H0, const uint32_t* L0,
                  const float* b0, float* C0,
                  const float* A1, const uint32_t* H1, const uint32_t* L1,
                  const float* b1, float* C1,
                  const float* A2, const uint32_t* H2, const uint32_t* L2,
                  const float* b2, float* C2) {
    const float* A; const uint32_t* H; const uint32_t* L; const float* bias; float* C;
    if (blockIdx.z == 0)      { A = A0; H = H0; L = L0; bias = b0; C = C0; }
    else if (blockIdx.z == 1) { A = A1; H = H1; L = L1; bias = b1; C = C1; }
    else                      { A = A2; H = H2; L = L2; bias = b2; C = C2; }
    tf32_gemm_core(A, H, L, bias, C);
}

// ---------------------------------------------------------------------------
// Weight transpose + tf32 split: Wt[z][n][k] = split(W[z][k][n])
// ---------------------------------------------------------------------------
__global__ void transpose_split_kernel(const float* __restrict__ Wi,
                                       const float* __restrict__ Wh,
                                       uint32_t* __restrict__ Wth,
                                       uint32_t* __restrict__ Wtl) {
    __shared__ float tile[32][33];
    int z = blockIdx.z;
    const float* src = (z < 2 ? Wi : Wh) + (size_t)(z & 1) * D_ * G_;
    uint32_t* dh = Wth + (size_t)z * GD;
    uint32_t* dl = Wtl + (size_t)z * GD;
    int n0 = blockIdx.x * 32, k0 = blockIdx.y * 32;
#pragma unroll
    for (int i = 0; i < 4; i++) {
        int k = k0 + threadIdx.y * 4 + i;
        tile[threadIdx.y * 4 + i][threadIdx.x] = src[(size_t)k * G_ + n0 + threadIdx.x];
    }
    __syncthreads();
#pragma unroll
    for (int i = 0; i < 4; i++) {
        int n = n0 + threadIdx.y * 4 + i;
        uint32_t hi, lo;
        split_tf32(tile[threadIdx.x][threadIdx.y * 4 + i], hi, lo);
        dh[(size_t)n * D_ + k0 + threadIdx.x] = hi;
        dl[(size_t)n * D_ + k0 + threadIdx.x] = lo;
    }
}

// ---------------------------------------------------------------------------
// Fused GRU cell + LayerNorm (128 thr x float4 = 512 = D)
// ---------------------------------------------------------------------------
__device__ __forceinline__ float sigf(float v) { return 1.f / (1.f + expf(-v)); }

__global__ void __launch_bounds__(128)
gru_cell(const float* __restrict__ gi_base, int t, int time_layout,
         const float* __restrict__ gh, float* __restrict__ h,
         const float* __restrict__ gamma, const float* __restrict__ beta,
         float* __restrict__ out2, int t_out) {
    int m = blockIdx.x;
    int b = m / N_, n = m % N_;
    const float* gi = gi_base +
        (time_layout ? ((size_t)(b * T_ + t) * N_ + n) : (size_t)m) * G_;
    const float4* gi4 = reinterpret_cast<const float4*>(gi);
    const float4* gh4 = reinterpret_cast<const float4*>(gh + (size_t)m * G_);
    float4* h4 = reinterpret_cast<float4*>(h + (size_t)m * D_);
    int tid = threadIdx.x;

    float4 ir = gi4[tid], iz = gi4[128 + tid], inn = gi4[256 + tid];
    float4 hr = gh4[tid], hz = gh4[128 + tid], hn = gh4[256 + tid];
    float4 hv = h4[tid];

    float o[4];
    {
        float rr, z, nv;
        rr = sigf(ir.x + hr.x); z = sigf(iz.x + hz.x); nv = tanhf(inn.x + rr * hn.x);
        o[0] = nv + z * (hv.x - nv);
        rr = sigf(ir.y + hr.y); z = sigf(iz.y + hz.y); nv = tanhf(inn.y + rr * hn.y);
        o[1] = nv + z * (hv.y - nv);
        rr = sigf(ir.z + hr.z); z = sigf(iz.z + hz.z); nv = tanhf(inn.z + rr * hn.z);
        o[2] = nv + z * (hv.z - nv);
        rr = sigf(ir.w + hr.w); z = sigf(iz.w + hz.w); nv = tanhf(inn.w + rr * hn.w);
        o[3] = nv + z * (hv.w - nv);
    }
    float s = o[0] + o[1] + o[2] + o[3];
    float s2 = o[0]*o[0] + o[1]*o[1] + o[2]*o[2] + o[3]*o[3];
#pragma unroll
    for (int off = 16; off > 0; off >>= 1) {
        s  += __shfl_xor_sync(0xffffffffu, s,  off);
        s2 += __shfl_xor_sync(0xffffffffu, s2, off);
    }
    __shared__ float sh[4], sh2[4];
    int w = tid >> 5;
    if ((tid & 31) == 0) { sh[w] = s; sh2[w] = s2; }
    __syncthreads();
    s  = sh[0]  + sh[1]  + sh[2]  + sh[3];
    s2 = sh2[0] + sh2[1] + sh2[2] + sh2[3];
    float mu  = s * (1.f / D_);
    float var = s2 * (1.f / D_) - mu * mu;
    float inv = rsqrtf(var + 1e-5f);

    const float4 g4 = reinterpret_cast<const float4*>(gamma)[tid];
    const float4 b4 = reinterpret_cast<const float4*>(beta)[tid];
    float4 y;
    y.x = (o[0] - mu) * inv * g4.x + b4.x;
    y.y = (o[1] - mu) * inv * g4.y + b4.y;
    y.z = (o[2] - mu) * inv * g4.z + b4.z;
    y.w = (o[3] - mu) * inv * g4.w + b4.w;
    h4[tid] = y;
    if (out2)
        reinterpret_cast<float4*>(out2 + ((size_t)(b * T_ + t_out) * N_ + n) * D_)[tid] = y;
}

// ---------------------------------------------------------------------------
__global__ void init_h_kernel(const float* __restrict__ h0,
                              float* __restrict__ h0s, float* __restrict__ h1s) {
    int i = blockIdx.x * blockDim.x + threadIdx.x;
    if (i >= 2 * MR * D_) return;
    int d = i % D_;
    int r = i / D_;
    int n = r % N_; r /= N_;
    int l = r % 2;
    int b = r / 2;
    float v = h0[i];
    float* dst = (l == 0) ? h0s : h1s;
    dst[((size_t)b * N_ + n) * D_ + d] = v;
}

__global__ void write_hidden_kernel(const float* __restrict__ h0s,
                                    const float* __restrict__ h1s,
                                    float* __restrict__ dst) {
    int i = blockIdx.x * blockDim.x + threadIdx.x;
    if (i >= 2 * MR * D_) return;
    int d = i % D_;
    int r = i / D_;
    int n = r % N_; r /= N_;
    int l = r % 2;
    int b = r / 2;
    const float* src = (l == 0) ? h0s : h1s;
    dst[i] = src[((size_t)b * N_ + n) * D_ + d];
}

// ---------------------------------------------------------------------------
extern "C" void kernel_launch(void* const* d_in, const int* in_sizes, int n_in,
                              void* d_out, int out_size) {
    (void)in_sizes; (void)n_in;
    const float* x     = (const float*)d_in[0];
    const float* h0    = (const float*)d_in[1];
    const float* Wi    = (const float*)d_in[2];
    const float* bi    = (const float*)d_in[3];
    const float* Wh    = (const float*)d_in[4];
    const float* bh    = (const float*)d_in[5];
    const float* gamma = (const float*)d_in[6];
    const float* beta  = (const float*)d_in[7];
    float* out = (float*)d_out;

    float *gi0, *gh0, *gi1, *gh1, *h0s, *h1s;
    uint32_t *Wth, *Wtl;
    cudaGetSymbolAddress((void**)&gi0, g_gi0);
    cudaGetSymbolAddress((void**)&gh0, g_gh0);
    cudaGetSymbolAddress((void**)&gi1, g_gi1);
    cudaGetSymbolAddress((void**)&gh1, g_gh1);
    cudaGetSymbolAddress((void**)&h0s, g_h0s);
    cudaGetSymbolAddress((void**)&h1s, g_h1s);
    cudaGetSymbolAddress((void**)&Wth, g_Wth);
    cudaGetSymbolAddress((void**)&Wtl, g_Wtl);

    cudaFuncSetAttribute(tf32_gemm1_kernel,
                         cudaFuncAttributeMaxDynamicSharedMemorySize, SMEM_BYTES);
    cudaFuncSetAttribute(tf32_gemm3_kernel,
                         cudaFuncAttributeMaxDynamicSharedMemorySize, SMEM_BYTES);

    const uint32_t* Wi0h = Wth;            const uint32_t* Wi0l = Wtl;
    const uint32_t* Wi1h = Wth + GD;       const uint32_t* Wi1l = Wtl + GD;
    const uint32_t* Wh0h = Wth + 2 * GD;   const uint32_t* Wh0l = Wtl + 2 * GD;
    const uint32_t* Wh1h = Wth + 3 * GD;   const uint32_t* Wh1l = Wtl + 3 * GD;

    transpose_split_kernel<<<dim3(G_ / 32, D_ / 32, 4), dim3(32, 8)>>>(Wi, Wh, Wth, Wtl);
    {
        int tot = 2 * MR * D_;
        init_h_kernel<<<(tot + 255) / 256, 256>>>(h0, h0s, h1s);
    }

    // Hoisted layer-0 input GEMM (all timesteps): gi0 = x @ Wi0 + bi0
    tf32_gemm1_kernel<<<dim3(G_ / 128, MB_ / 128), 256, SMEM_BYTES>>>(x, Wi0h, Wi0l, bi, gi0);

    // GH0(0) = h0 @ Wh0 + bh0, then cell0(0)
    tf32_gemm1_kernel<<<dim3(G_ / 128, MRP / 128), 256, SMEM_BYTES>>>(h0s, Wh0h, Wh0l, bh, gh0);
    gru_cell<<<MR, 128>>>(gi0, 0, 1, gh0, h0s, gamma, beta, (float*)nullptr, 0);

    for (int t = 0; t < T_; t++) {
        int nz = (t == T_ - 1) ? 2 : 3;
        // z=0: GI1(t)=out0(t)@Wi1 ; z=1: GH1(t)=h1@Wh1 ; z=2: GH0(t+1)=out0(t)@Wh0
        tf32_gemm3_kernel<<<dim3(G_ / 128, MRP / 128, nz), 256, SMEM_BYTES>>>(
            h0s, Wi1h, Wi1l, bi + G_, gi1,
            h1s, Wh1h, Wh1l, bh + G_, gh1,
            h0s, Wh0h, Wh0l, bh,      gh0);
        gru_cell<<<MR, 128>>>(gi1, 0, 0, gh1, h1s, gamma + D_, beta + D_, out, t);
        if (t + 1 < T_)
            gru_cell<<<MR, 128>>>(gi0, t + 1, 1, gh0, h0s, gamma, beta,
                                  (float*)nullptr, 0);
    }

    long long need = (long long)MB_ * D_ + (long long)2 * MR * D_;
    if ((long long)out_size >= need) {
        int tot = 2 * MR * D_;
        write_hidden_kernel<<<(tot + 255) / 256, 256>>>(h0s, h1s,
                                                        out + (size_t)MB_ * D_);
    }
}

// round 5
// speedup vs baseline: 1.6915x; 1.1351x over previous
#include <cuda_runtime.h>
#include <math.h>
#include <stdint.h>

// GraphRNN: 2-layer LayerNorm-GRU scan. B=16, T=24, N=207, D=512, G=1536.
// R5: mma.sync m16n8k8 tf32 3x-split; fragment-packed weights (LDS.128),
//     pass-reordered MMAs for accumulator latency hiding.
namespace {
constexpr int B_ = 16, T_ = 24, N_ = 207, D_ = 512, G_ = 1536;
constexpr int MR  = B_ * N_;        // 3312 rows per timestep
constexpr int MRP = 3328;           // padded: 26*128
constexpr int MB_ = B_ * T_ * N_;   // 79488 = 621*128

constexpr int BK = 32;              // k-chunk
constexpr int NCHUNK = D_ / BK;     // 16
constexpr int LDP = 36;             // A smem row stride: bank=(4r+qk)%32 bijective
constexpr int A_STAGE_F = 128 * LDP;        // 4608 floats
constexpr int B_STAGE_Q = 2048;             // 16g*4k8*32lane quads (32KB)
constexpr int SMEM_BYTES = 2 * A_STAGE_F * 4 + 2 * B_STAGE_Q * 16;  // 102400

constexpr int CT_ = G_ / 128;       // 12 col-tiles
constexpr int WQ_PER_W = CT_ * NCHUNK * B_STAGE_Q;  // 393216 quads per weight
}

// ---------------- scratch (device globals) ----------------
__device__ float g_gi0[(size_t)MB_ * G_];
__device__ float g_gh0[(size_t)MRP * G_];
__device__ float g_gi1[(size_t)MRP * G_];
__device__ float g_gh1[(size_t)MRP * G_];
__device__ float g_h0s[(size_t)MRP * D_];   // pad rows stay 0
__device__ float g_h1s[(size_t)MRP * D_];
__device__ uint4 g_Wp[4 * (size_t)WQ_PER_W];  // packed Wi0,Wi1,Wh0,Wh1

// ---------------- helpers ----------------
__device__ __forceinline__ uint32_t smem_u32(const void* p) {
    uint32_t a;
    asm("{ .reg .u64 t; cvta.to.shared.u64 t, %1; cvt.u32.u64 %0, t; }"
        : "=r"(a) : "l"(p));
    return a;
}
#define CP_ASYNC16(dst, src) \
    asm volatile("cp.async.cg.shared.global [%0], [%1], 16;" :: "r"(dst), "l"(src))
#define CP_COMMIT() asm volatile("cp.async.commit_group;" ::: "memory")
template <int N>
__device__ __forceinline__ void cp_wait() {
    asm volatile("cp.async.wait_group %0;" :: "n"(N) : "memory");
}

__device__ __forceinline__ uint32_t cvt_tf32(float x) {
    uint32_t r;
    asm("cvt.rna.tf32.f32 %0, %1;" : "=r"(r) : "f"(x));
    return r;
}
__device__ __forceinline__ void split_tf32(float x, uint32_t& hi, uint32_t& lo) {
    hi = cvt_tf32(x);
    lo = cvt_tf32(x - __uint_as_float(hi));
}

#define MMA_TF32(d, a, b0, b1)                                              \
    asm volatile("mma.sync.aligned.m16n8k8.row.col.f32.tf32.tf32.f32 "      \
        "{%0,%1,%2,%3}, {%4,%5,%6,%7}, {%8,%9}, {%0,%1,%2,%3};"             \
        : "+f"((d)[0]), "+f"((d)[1]), "+f"((d)[2]), "+f"((d)[3])            \
        : "r"((a)[0]), "r"((a)[1]), "r"((a)[2]), "r"((a)[3]),               \
          "r"(b0), "r"(b1))

// ---------------------------------------------------------------------------
// GEMM core: C tile (128x128) = A[brow..,512] @ W[bcol..]^T + bias
// A fp32 K-major; W fragment-packed (hi/lo tf32 quads). 256 thr, 8 warps.
// ---------------------------------------------------------------------------
__device__ __forceinline__ void load_stage(uint32_t sA, uint32_t sB,
                                           const float* __restrict__ Ag,
                                           const uint4* __restrict__ Bq,
                                           int ch, int tid) {
    const int k0 = ch * BK;
#pragma unroll
    for (int i = 0; i < 4; i++) {
        int s = tid + i * 256;          // 0..1023 16B slots of A
        int row = s >> 3, c4 = s & 7;
        uint32_t doff = (uint32_t)(row * LDP + c4 * 4) * 4u;
        CP_ASYNC16(sA + doff, Ag + (size_t)row * D_ + k0 + c4 * 4);
    }
    const uint4* src = Bq + (size_t)ch * B_STAGE_Q;
#pragma unroll
    for (int i = 0; i < 8; i++) {
        int s = tid + i * 256;          // 0..2047 quads of packed B
        CP_ASYNC16(sB + (uint32_t)s * 16u, src + s);
    }
}

__device__ __forceinline__ void tf32_gemm_core(const float* __restrict__ A,
                                               const uint4* __restrict__ Wp,
                                               const float* __restrict__ bias,
                                               float* __restrict__ C) {
    extern __shared__ float sm[];
    float* AsT[2] = { sm, sm + A_STAGE_F };
    uint4* BsT[2] = { (uint4*)(sm + 2 * A_STAGE_F),
                      (uint4*)(sm + 2 * A_STAGE_F) + B_STAGE_Q };

    const int tid  = threadIdx.x;
    const int lane = tid & 31, warp = tid >> 5;
    const int warpM = warp & 3, warpN = warp >> 2;
    const int r  = lane >> 2;       // 0..7
    const int qk = lane & 3;        // 0..3
    const int brow = blockIdx.y * 128;

    const float* Ag = A + (size_t)brow * D_;
    const uint4* Bq = Wp + (size_t)blockIdx.x * (NCHUNK * B_STAGE_Q);

    float acc[2][8][4];
#pragma unroll
    for (int mt = 0; mt < 2; mt++)
#pragma unroll
        for (int nt = 0; nt < 8; nt++)
#pragma unroll
            for (int i = 0; i < 4; i++) acc[mt][nt][i] = 0.f;

    load_stage(smem_u32(AsT[0]), smem_u32(BsT[0]), Ag, Bq, 0, tid);
    CP_COMMIT();
    load_stage(smem_u32(AsT[1]), smem_u32(BsT[1]), Ag, Bq, 1, tid);
    CP_COMMIT();

    for (int ch = 0; ch < NCHUNK; ch++) {
        if (ch < NCHUNK - 1) cp_wait<1>(); else cp_wait<0>();
        __syncthreads();
        const int cur = ch & 1;
        const float* as = AsT[cur] + (size_t)(warpM * 32 + r) * LDP;
        // warp's B fragments: quad index ((g*4 + k8)*32 + lane), g = warpN*8+nt
        const uint4* bw = BsT[cur] + ((size_t)warpN * 8 * 4) * 32 + lane;

#pragma unroll
        for (int k8 = 0; k8 < 4; k8++) {
            const int kk = k8 * 8 + qk;
            uint32_t ah[2][4], al[2][4];
#pragma unroll
            for (int mt = 0; mt < 2; mt++) {
                const float* p = as + mt * 16 * LDP;
                split_tf32(p[kk],                ah[mt][0], al[mt][0]);
                split_tf32(p[8 * LDP + kk],      ah[mt][1], al[mt][1]);
                split_tf32(p[kk + 4],            ah[mt][2], al[mt][2]);
                split_tf32(p[8 * LDP + kk + 4],  ah[mt][3], al[mt][3]);
            }
#pragma unroll
            for (int half = 0; half < 2; half++) {
                uint4 bf[4];
#pragma unroll
                for (int j = 0; j < 4; j++)
                    bf[j] = bw[((half * 4 + j) * 4 + k8) * 32];
                // pass 1: al * bh
#pragma unroll
                for (int j = 0; j < 4; j++)
#pragma unroll
                    for (int mt = 0; mt < 2; mt++)
                        MMA_TF32(acc[mt][half * 4 + j], al[mt], bf[j].x, bf[j].y);
                // pass 2: ah * bl
#pragma unroll
                for (int j = 0; j < 4; j++)
#pragma unroll
                    for (int mt = 0; mt < 2; mt++)
                        MMA_TF32(acc[mt][half * 4 + j], ah[mt], bf[j].z, bf[j].w);
                // pass 3: ah * bh
#pragma unroll
                for (int j = 0; j < 4; j++)
#pragma unroll
                    for (int mt = 0; mt < 2; mt++)
                        MMA_TF32(acc[mt][half * 4 + j], ah[mt], bf[j].x, bf[j].y);
            }
        }
        __syncthreads();
        if (ch + 2 < NCHUNK) {
            load_stage(smem_u32(AsT[cur]), smem_u32(BsT[cur]), Ag, Bq, ch + 2, tid);
            CP_COMMIT();
        }
    }

    // epilogue: acc + bias -> C (float2 stores)
    const int bcol = blockIdx.x * 128;
    const int q2 = qk * 2;
#pragma unroll
    for (int mt = 0; mt < 2; mt++) {
        const int row0 = brow + warpM * 32 + mt * 16 + r;
#pragma unroll
        for (int nt = 0; nt < 8; nt++) {
            const int col = bcol + warpN * 64 + nt * 8 + q2;
            const float2 bv = *reinterpret_cast<const float2*>(bias + col);
            float2 v0 = make_float2(acc[mt][nt][0] + bv.x, acc[mt][nt][1] + bv.y);
            float2 v1 = make_float2(acc[mt][nt][2] + bv.x, acc[mt][nt][3] + bv.y);
            *reinterpret_cast<float2*>(C + (size_t)row0 * G_ + col) = v0;
            *reinterpret_cast<float2*>(C + (size_t)(row0 + 8) * G_ + col) = v1;
        }
    }
}

__global__ void __launch_bounds__(256, 2)
tf32_gemm1_kernel(const float* __restrict__ A, const uint4* __restrict__ Wp,
                  const float* __restrict__ bias, float* __restrict__ C) {
    tf32_gemm_core(A, Wp, bias, C);
}

__global__ void __launch_bounds__(256, 2)
tf32_gemm3_kernel(const float* A0, const uint4* P0, const float* b0, float* C0,
                  const float* A1, const uint4* P1, const float* b1, float* C1,
                  const float* A2, const uint4* P2, const float* b2, float* C2) {
    const float* A; const uint4* P; const float* bias; float* C;
    if (blockIdx.z == 0)      { A = A0; P = P0; bias = b0; C = C0; }
    else if (blockIdx.z == 1) { A = A1; P = P1; bias = b1; C = C1; }
    else                      { A = A2; P = P2; bias = b2; C = C2; }
    tf32_gemm_core(A, P, bias, C);
}

// ---------------------------------------------------------------------------
// Weight prepack: W[k][n] -> fragment quads [bh(k), bh(k+4), bl(k), bl(k+4)]
// layout: [z][ct][ch][g][k8][lane] quads; block=(ct,ch,z), 256 threads.
// ---------------------------------------------------------------------------
__global__ void prepack_kernel(const float* __restrict__ Wi,
                               const float* __restrict__ Wh,
                               uint4* __restrict__ Wp) {
    __shared__ float tile[32][128];
    const int ct = blockIdx.x, ch = blockIdx.y, z = blockIdx.z;
    const float* src = (z < 2 ? Wi : Wh) + (size_t)(z & 1) * D_ * G_;
    const int tid = threadIdx.x;

    // coalesced load: 32 k-rows x 128 n-cols
#pragma unroll
    for (int i = 0; i < 16; i++) {
        int s = tid + i * 256;          // 0..4095
        int kk = s >> 7, n = s & 127;
        tile[kk][n] = src[(size_t)(ch * 32 + kk) * G_ + ct * 128 + n];
    }
    __syncthreads();

    uint4* dst = Wp + ((size_t)z * CT_ * NCHUNK + (size_t)ct * NCHUNK + ch) * B_STAGE_Q;
#pragma unroll
    for (int i = 0; i < 8; i++) {
        int e = tid + i * 256;          // 0..2047
        int g = e >> 7, k8 = (e >> 5) & 3, ln = e & 31;
        int rr = ln >> 2, qq = ln & 3;
        int nl = g * 8 + rr;
        int kl = k8 * 8 + qq;
        uint32_t h0, l0, h1, l1;
        split_tf32(tile[kl][nl],     h0, l0);
        split_tf32(tile[kl + 4][nl], h1, l1);
        uint4 q; q.x = h0; q.y = h1; q.z = l0; q.w = l1;
        dst[e] = q;
    }
}

// ---------------------------------------------------------------------------
// Fused GRU cell + LayerNorm (128 thr x float4 = 512 = D)
// ---------------------------------------------------------------------------
__device__ __forceinline__ float sigf(float v) { return 1.f / (1.f + expf(-v)); }

__global__ void __launch_bounds__(128)
gru_cell(const float* __restrict__ gi_base, int t, int time_layout,
         const float* __restrict__ gh, float* __restrict__ h,
         const float* __restrict__ gamma, const float* __restrict__ beta,
         float* __restrict__ out2, int t_out) {
    int m = blockIdx.x;
    int b = m / N_, n = m % N_;
    const float* gi = gi_base +
        (time_layout ? ((size_t)(b * T_ + t) * N_ + n) : (size_t)m) * G_;
    const float4* gi4 = reinterpret_cast<const float4*>(gi);
    const float4* gh4 = reinterpret_cast<const float4*>(gh + (size_t)m * G_);
    float4* h4 = reinterpret_cast<float4*>(h + (size_t)m * D_);
    int tid = threadIdx.x;

    float4 ir = gi4[tid], iz = gi4[128 + tid], inn = gi4[256 + tid];
    float4 hr = gh4[tid], hz = gh4[128 + tid], hn = gh4[256 + tid];
    float4 hv = h4[tid];

    float o[4];
    {
        float rr, z, nv;
        rr = sigf(ir.x + hr.x); z = sigf(iz.x + hz.x); nv = tanhf(inn.x + rr * hn.x);
        o[0] = nv + z * (hv.x - nv);
        rr = sigf(ir.y + hr.y); z = sigf(iz.y + hz.y); nv = tanhf(inn.y + rr * hn.y);
        o[1] = nv + z * (hv.y - nv);
        rr = sigf(ir.z + hr.z); z = sigf(iz.z + hz.z); nv = tanhf(inn.z + rr * hn.z);
        o[2] = nv + z * (hv.z - nv);
        rr = sigf(ir.w + hr.w); z = sigf(iz.w + hz.w); nv = tanhf(inn.w + rr * hn.w);
        o[3] = nv + z * (hv.w - nv);
    }
    float s = o[0] + o[1] + o[2] + o[3];
    float s2 = o[0]*o[0] + o[1]*o[1] + o[2]*o[2] + o[3]*o[3];
#pragma unroll
    for (int off = 16; off > 0; off >>= 1) {
        s  += __shfl_xor_sync(0xffffffffu, s,  off);
        s2 += __shfl_xor_sync(0xffffffffu, s2, off);
    }
    __shared__ float sh[4], sh2[4];
    int w = tid >> 5;
    if ((tid & 31) == 0) { sh[w] = s; sh2[w] = s2; }
    __syncthreads();
    s  = sh[0]  + sh[1]  + sh[2]  + sh[3];
    s2 = sh2[0] + sh2[1] + sh2[2] + sh2[3];
    float mu  = s * (1.f / D_);
    float var = s2 * (1.f / D_) - mu * mu;
    float inv = rsqrtf(var + 1e-5f);

    const float4 g4 = reinterpret_cast<const float4*>(gamma)[tid];
    const float4 b4 = reinterpret_cast<const float4*>(beta)[tid];
    float4 y;
    y.x = (o[0] - mu) * inv * g4.x + b4.x;
    y.y = (o[1] - mu) * inv * g4.y + b4.y;
    y.z = (o[2] - mu) * inv * g4.z + b4.z;
    y.w = (o[3] - mu) * inv * g4.w + b4.w;
    h4[tid] = y;
    if (out2)
        reinterpret_cast<float4*>(out2 + ((size_t)(b * T_ + t_out) * N_ + n) * D_)[tid] = y;
}

// ---------------------------------------------------------------------------
__global__ void init_h_kernel(const float* __restrict__ h0,
                              float* __restrict__ h0s, float* __restrict__ h1s) {
    int i = blockIdx.x * blockDim.x + threadIdx.x;
    if (i >= 2 * MR * D_) return;
    int d = i % D_;
    int r = i / D_;
    int n = r % N_; r /= N_;
    int l = r % 2;
    int b = r / 2;
    float v = h0[i];
    float* dst = (l == 0) ? h0s : h1s;
    dst[((size_t)b * N_ + n) * D_ + d] = v;
}

__global__ void write_hidden_kernel(const float* __restrict__ h0s,
                                    const float* __restrict__ h1s,
                                    float* __restrict__ dst) {
    int i = blockIdx.x * blockDim.x + threadIdx.x;
    if (i >= 2 * MR * D_) return;
    int d = i % D_;
    int r = i / D_;
    int n = r % N_; r /= N_;
    int l = r % 2;
    int b = r / 2;
    const float* src = (l == 0) ? h0s : h1s;
    dst[i] = src[((size_t)b * N_ + n) * D_ + d];
}

// ---------------------------------------------------------------------------
extern "C" void kernel_launch(void* const* d_in, const int* in_sizes, int n_in,
                              void* d_out, int out_size) {
    (void)in_sizes; (void)n_in;
    const float* x     = (const float*)d_in[0];
    const float* h0    = (const float*)d_in[1];
    const float* Wi    = (const float*)d_in[2];
    const float* bi    = (const float*)d_in[3];
    const float* Wh    = (const float*)d_in[4];
    const float* bh    = (const float*)d_in[5];
    const float* gamma = (const float*)d_in[6];
    const float* beta  = (const float*)d_in[7];
    float* out = (float*)d_out;

    float *gi0, *gh0, *gi1, *gh1, *h0s, *h1s;
    uint4* Wp;
    cudaGetSymbolAddress((void**)&gi0, g_gi0);
    cudaGetSymbolAddress((void**)&gh0, g_gh0);
    cudaGetSymbolAddress((void**)&gi1, g_gi1);
    cudaGetSymbolAddress((void**)&gh1, g_gh1);
    cudaGetSymbolAddress((void**)&h0s, g_h0s);
    cudaGetSymbolAddress((void**)&h1s, g_h1s);
    cudaGetSymbolAddress((void**)&Wp,  g_Wp);

    cudaFuncSetAttribute(tf32_gemm1_kernel,
                         cudaFuncAttributeMaxDynamicSharedMemorySize, SMEM_BYTES);
    cudaFuncSetAttribute(tf32_gemm3_kernel,
                         cudaFuncAttributeMaxDynamicSharedMemorySize, SMEM_BYTES);

    const uint4* Wi0p = Wp;
    const uint4* Wi1p = Wp + (size_t)WQ_PER_W;
    const uint4* Wh0p = Wp + (size_t)2 * WQ_PER_W;
    const uint4* Wh1p = Wp + (size_t)3 * WQ_PER_W;

    prepack_kernel<<<dim3(CT_, NCHUNK, 4), 256>>>(Wi, Wh, Wp);
    {
        int tot = 2 * MR * D_;
        init_h_kernel<<<(tot + 255) / 256, 256>>>(h0, h0s, h1s);
    }

    // Hoisted layer-0 input GEMM (all timesteps): gi0 = x @ Wi0 + bi0
    tf32_gemm1_kernel<<<dim3(CT_, MB_ / 128), 256, SMEM_BYTES>>>(x, Wi0p, bi, gi0);

    // GH0(0) = h0 @ Wh0 + bh0, then cell0(0)
    tf32_gemm1_kernel<<<dim3(CT_, MRP / 128), 256, SMEM_BYTES>>>(h0s, Wh0p, bh, gh0);
    gru_cell<<<MR, 128>>>(gi0, 0, 1, gh0, h0s, gamma, beta, (float*)nullptr, 0);

    for (int t = 0; t < T_; t++) {
        int nz = (t == T_ - 1) ? 2 : 3;
        // z=0: GI1(t)=out0(t)@Wi1 ; z=1: GH1(t)=h1@Wh1 ; z=2: GH0(t+1)=out0(t)@Wh0
        tf32_gemm3_kernel<<<dim3(CT_, MRP / 128, nz), 256, SMEM_BYTES>>>(
            h0s, Wi1p, bi + G_, gi1,
            h1s, Wh1p, bh + G_, gh1,
            h0s, Wh0p, bh,      gh0);
        gru_cell<<<MR, 128>>>(gi1, 0, 0, gh1, h1s, gamma + D_, beta + D_, out, t);
        if (t + 1 < T_)
            gru_cell<<<MR, 128>>>(gi0, t + 1, 1, gh0, h0s, gamma, beta,
                                  (float*)nullptr, 0);
    }

    long long need = (long long)MB_ * D_ + (long long)2 * MR * D_;
    if ((long long)out_size >= need) {
        int tot = 2 * MR * D_;
        write_hidden_kernel<<<(tot + 255) / 256, 256>>>(h0s, h1s,
                                                        out + (size_t)MB_ * D_);
    }
}